// round 11
// baseline (speedup 1.0000x reference)
#include <cuda_runtime.h>
#include <math.h>
#include <stdint.h>

#define BB   16
#define NN   256
#define DD   64
#define KTOP 128
#define NT   8          // 256/32 tiles per dim
#define NPAIR 36        // NT*(NT+1)/2

// Scratch (no device allocations allowed)
__device__ float g_logits[BB * NN * NN];   // 4 MB
__device__ float g_h[BB * NN * DD];
__device__ float g_scores[BB * NN];
__device__ int   g_cnt[BB];                // zero-init; returns to 0 each launch

// ---------------- packed f32x2 helpers ----------------
__device__ __forceinline__ unsigned long long pack2f(float a, float b) {
    unsigned long long r;
    asm("mov.b64 %0, {%1, %2};" : "=l"(r) : "f"(a), "f"(b));
    return r;
}
__device__ __forceinline__ void fma2(unsigned long long& d,
                                     unsigned long long a,
                                     unsigned long long b) {
    asm("fma.rn.f32x2 %0, %1, %2, %0;" : "+l"(d) : "l"(a), "l"(b));
}
__device__ __forceinline__ float2 unpack2f(unsigned long long v) {
    float lo, hi;
    asm("mov.b64 {%0, %1}, %2;" : "=f"(lo), "=f"(hi) : "l"(v));
    float2 r; r.x = lo; r.y = hi;
    return r;
}
__device__ __forceinline__ float ex2f(float x) {
    float y; asm("ex2.approx.f32 %0, %1;" : "=f"(y) : "f"(x)); return y;
}
__device__ __forceinline__ float rcpf(float x) {
    float y; asm("rcp.approx.f32 %0, %1;" : "=f"(y) : "f"(x)); return y;
}

#define C2LOG2E 2.8853900817779268f   // 2*log2(e)
#define LOG2E   1.4426950408889634f

// ---------------- k1a smem layout (bytes) ----------------
#define SM_XIP  0                      // [64][16] u64  i-pair scalars
#define SM_XJ   8192                   // [64][36] f32  plain j values
#define SM_W2   17408                  // [64][36] u64  W natural pairs
#define SM_EP   35840                  // [32][68] f32  partial logits (8704)
#define SM_BW   44544                  // 64 float2
#define SM_BASE 45056                  // 2 f32 (+pad)
#define SM_TILE 45072                  // [32][33] f32
#define SM_TOT1 (SM_TILE + 4224)       // 49296

// =====================================================================
// Kernel 1a: symmetric logits. grid (36 tile-pairs, 16 b), block 256.
// Sync-free pass loop (disjoint ep regions) + round-8 epilogue
// (4 independent rcp chains) — isolates the round-9 confound.
// =====================================================================
__global__ __launch_bounds__(256, 2)
void k1a_logits(const float* __restrict__ x,
                const float* __restrict__ Watt,
                const float* __restrict__ batt_g,
                const float* __restrict__ attw_g)
{
    extern __shared__ char sm[];
    unsigned long long* xip = (unsigned long long*)(sm + SM_XIP);
    float* xjs  = (float*)(sm + SM_XJ);
    unsigned long long* w2 = (unsigned long long*)(sm + SM_W2);
    float*  ep   = (float*)(sm + SM_EP);
    float2* bw2  = (float2*)(sm + SM_BW);
    float*  base = (float*)(sm + SM_BASE);
    float*  tile = (float*)(sm + SM_TILE);

    const int tid = threadIdx.x;
    const int b   = blockIdx.y;

    // decode triangle tile pair
    int p = blockIdx.x, ti = 0;
    while (p >= NT - ti) { p -= NT - ti; ++ti; }
    const int tj = ti + p;
    const int i0 = ti * 32, j0 = tj * 32;

    const float* xb = x + (size_t)b * NN * DD;

    for (int t = tid; t < 1024; t += 256) {          // xip[d][ipg]
        int ipg = t >> 6, d = t & 63;
        float a = xb[(size_t)(i0 + 2 * ipg) * DD + d];
        float c = xb[(size_t)(i0 + 2 * ipg + 1) * DD + d];
        xip[d * 16 + ipg] = pack2f(a, c);
    }
    for (int t = tid; t < 2048; t += 256) {          // xj[d][j] plain
        int j = t >> 6, d = t & 63;
        xjs[d * 36 + j] = xb[(size_t)(j0 + j) * DD + d];
    }
    for (int t = tid; t < 2048; t += 256) {          // w2[d][slot] natural pairs
        int d = t >> 5, k = t & 31;
        float2 w = ((const float2*)Watt)[t];
        int slot = (k < 16) ? k : (k + 2);           // eh=1 half at +18
        w2[d * 36 + slot] = pack2f(w.x, w.y);
    }
    if (tid < 64) {
        float aww = attw_g[tid];
        bw2[tid] = make_float2(batt_g[tid] * C2LOG2E, -aww);
    }
    __syncthreads();
    if (tid < 2) {
        float s = 0.f;
        #pragma unroll
        for (int e = 0; e < 32; ++e) s -= bw2[tid * 32 + e].y;   // +aw
        base[tid] = 0.5f * s;
    }
    __syncthreads();

    const int ip = tid >> 6;            // 0..3
    const int jl = (tid >> 1) & 31;     // j lane
    const int eh = tid & 1;             // e half

    const float* xj_p = xjs + jl;
    const char* w_p = (const char*)(w2 + eh * 18);
    const float bs = base[eh];
    const float2* bwh = bw2 + eh * 32;

    for (int pass = 0; pass < 4; ++pass) {
        unsigned long long acc0[16], acc1[16];
        #pragma unroll
        for (int k = 0; k < 16; ++k) { acc0[k] = 0ull; acc1[k] = 0ull; }

        const unsigned long long* xv = xip + (pass * 4 + ip);

        #pragma unroll 4
        for (int d = 0; d < 64; ++d) {
            float2 xi2 = unpack2f(xv[d * 16]);
            float xjv = xj_p[d * 36];
            float f0 = xi2.x * xjv, f1 = xi2.y * xjv;
            unsigned long long pp0 = pack2f(f0, f0);
            unsigned long long pp1 = pack2f(f1, f1);
            const ulonglong2* wr = (const ulonglong2*)(w_p + d * 288);
            #pragma unroll
            for (int h = 0; h < 8; ++h) {
                ulonglong2 wv = wr[h];
                fma2(acc0[2 * h + 0], pp0, wv.x);
                fma2(acc0[2 * h + 1], pp0, wv.y);
                fma2(acc1[2 * h + 0], pp1, wv.x);
                fma2(acc1[2 * h + 1], pp1, wv.y);
            }
        }

        // round-8 epilogue: 4 independent rcp chains per k
        float pl0 = bs, pl1 = bs;
        #pragma unroll
        for (int k = 0; k < 16; ++k) {
            float2 bc0 = bwh[2 * k], bc1 = bwh[2 * k + 1];
            float2 v0 = unpack2f(acc0[k]);
            float2 v1 = unpack2f(acc1[k]);
            float r00 = rcpf(ex2f(fmaf(v0.x, C2LOG2E, bc0.x)) + 1.f);
            float r01 = rcpf(ex2f(fmaf(v0.y, C2LOG2E, bc1.x)) + 1.f);
            float r10 = rcpf(ex2f(fmaf(v1.x, C2LOG2E, bc0.x)) + 1.f);
            float r11 = rcpf(ex2f(fmaf(v1.y, C2LOG2E, bc1.x)) + 1.f);
            pl0 = fmaf(bc0.y, r00, pl0);
            pl0 = fmaf(bc1.y, r01, pl0);
            pl1 = fmaf(bc0.y, r10, pl1);
            pl1 = fmaf(bc1.y, r11, pl1);
        }
        {
            int r0 = (pass * 4 + ip) * 2;
            ep[r0 * 68 + jl * 2 + eh] = pl0;
            ep[(r0 + 1) * 68 + jl * 2 + eh] = pl1;
        }
        // NO sync: each pass writes a disjoint ep region
    }
    __syncthreads();

    // combine eh halves for all 32 rows; store direct + stage tile
    {
        int i_loc = tid >> 3, jq = tid & 7;
        const float* er = ep + i_loc * 68 + jq * 8;
        float4 lo = *(const float4*)(er);
        float4 hi = *(const float4*)(er + 4);
        float4 lg = make_float4(lo.x + lo.y, lo.z + lo.w,
                                hi.x + hi.y, hi.z + hi.w);
        *(float4*)(&g_logits[((size_t)b * NN + i0 + i_loc) * NN + j0 + jq * 4]) = lg;
        float* tr = tile + i_loc * 33 + jq * 4;
        tr[0] = lg.x; tr[1] = lg.y; tr[2] = lg.z; tr[3] = lg.w;
    }
    __syncthreads();

    // coalesced mirror store (off-diagonal tiles only)
    if (ti != tj) {
        #pragma unroll
        for (int k = 0; k < 4; ++k) {
            int jj = (tid >> 5) + k * 8;
            int col = tid & 31;
            g_logits[((size_t)b * NN + j0 + jj) * NN + i0 + col] =
                tile[col * 33 + jj];
        }
    }
}

// ---------------- k1b2 smem layout (bytes) ----------------
#define SMB_XS  0                      // 256*64 f32 = 65536
#define SMB_WA  65536                  // [d][e] 64*64 f32 = 16384
#define SMB_WN  81920                  // 16384
#define SMB_AG  98304                  // [32][64] f32 = 8192 (reused for topk)
#define SMB_PRM 106496                 // 5*64+8 f32
#define SMB_TOT (106496 + 1312)

// =====================================================================
// Kernel 1b2: softmax + agg + linear + BN + SELU + scores
//             + last-CTA-per-batch top-k + gather (k3 fused).
// grid (8, 16), block 256 (8 warps).
// =====================================================================
__global__ __launch_bounds__(256, 2)
void k1b2_fused(const float* __restrict__ x,
                const float* __restrict__ Wpwa, const float* __restrict__ bpwa,
                const float* __restrict__ Wpna, const float* __restrict__ bpna,
                const float* __restrict__ bnsc, const float* __restrict__ bnbi,
                const float* __restrict__ poolw, const float* __restrict__ poolb,
                float* __restrict__ out)
{
    extern __shared__ char sm2[];
    float* xs   = (float*)(sm2 + SMB_XS);
    float* Wa   = (float*)(sm2 + SMB_WA);
    float* Wn   = (float*)(sm2 + SMB_WN);
    float* aggs = (float*)(sm2 + SMB_AG);
    float* prm  = (float*)(sm2 + SMB_PRM);

    const int tid = threadIdx.x;
    const int lane = tid & 31, w = tid >> 5;
    const int b  = blockIdx.y;
    const int i0 = blockIdx.x * 32;
    const float* xb = x + (size_t)b * NN * DD;

    // stage x_b (64KB), W's (natural [d][e] layout), params
    for (int t = tid; t < 4096; t += 256)
        ((float4*)xs)[t] = ((const float4*)xb)[t];
    for (int t = tid; t < 1024; t += 256) {
        ((float4*)Wa)[t] = ((const float4*)Wpwa)[t];
        ((float4*)Wn)[t] = ((const float4*)Wpna)[t];
    }
    if (tid < 64) {
        prm[tid]       = bpwa[tid] + bpna[tid];
        prm[64 + tid]  = bnsc[tid] * rsqrtf(1.0f + 1e-5f);
        prm[128 + tid] = bnbi[tid];
        prm[192 + tid] = poolw[tid];
    }
    if (tid == 0) prm[320] = poolb[0];
    __syncthreads();

    const int d0 = lane * 2;
    const int e0 = lane * 2;

    for (int c = 0; c < 4; ++c) {
        const int iL = w * 4 + c;          // local 0..31
        const int ig = i0 + iL;            // global node

        // ---- softmax over 256 j (warp-only) ----
        const float* lrow = g_logits + ((size_t)b * NN + ig) * NN;
        float4 va = ((const float4*)lrow)[lane];
        float4 vb = ((const float4*)lrow)[32 + lane];
        float av[8] = { va.x, va.y, va.z, va.w, vb.x, vb.y, vb.z, vb.w };

        float m = av[0];
        #pragma unroll
        for (int k = 1; k < 8; ++k) m = fmaxf(m, av[k]);
        #pragma unroll
        for (int o = 16; o; o >>= 1) m = fmaxf(m, __shfl_xor_sync(0xffffffffu, m, o));

        float s = 0.f;
        #pragma unroll
        for (int k = 0; k < 8; ++k) { av[k] = ex2f((av[k] - m) * LOG2E); s += av[k]; }
        #pragma unroll
        for (int o = 16; o; o >>= 1) s += __shfl_xor_sync(0xffffffffu, s, o);
        float inv = 1.f / s;
        #pragma unroll
        for (int k = 0; k < 8; ++k) av[k] *= inv;

        // ---- agg[d0,d0+1] = sum_j A[j] * x[j][d] (smem, shuffle bcast) ----
        float ax0 = 0.f, ay0 = 0.f, ax1 = 0.f, ay1 = 0.f;
        #pragma unroll 4
        for (int src = 0; src < 32; ++src) {
            #pragma unroll
            for (int k = 0; k < 8; ++k) {
                float A = __shfl_sync(0xffffffffu, av[k], src);
                int j = src * 4 + (k & 3) + ((k & 4) << 5);
                float2 xv = *(const float2*)(xs + j * 64 + d0);
                if (k < 4) { ax0 = fmaf(A, xv.x, ax0); ay0 = fmaf(A, xv.y, ay0); }
                else       { ax1 = fmaf(A, xv.x, ax1); ay1 = fmaf(A, xv.y, ay1); }
            }
        }
        *(float2*)(aggs + iL * 64 + d0) = make_float2(ax0 + ax1, ay0 + ay1);
        __syncwarp();

        // ---- linear + BN + SELU + score (warp-only) ----
        float ha0 = 0.f, ha1 = 0.f, hn0 = 0.f, hn1 = 0.f;
        #pragma unroll 8
        for (int d = 0; d < 64; ++d) {
            float ad = aggs[iL * 64 + d];
            float xd = xs[ig * 64 + d];
            float2 wa = *(const float2*)(Wa + d * 64 + e0);
            float2 wn = *(const float2*)(Wn + d * 64 + e0);
            ha0 = fmaf(ad, wa.x, ha0); ha1 = fmaf(ad, wa.y, ha1);
            hn0 = fmaf(xd, wn.x, hn0); hn1 = fmaf(xd, wn.y, hn1);
        }
        float h0 = ha0 + hn0 + prm[e0];
        float h1 = ha1 + hn1 + prm[e0 + 1];
        h0 = h0 * prm[64 + e0] + prm[128 + e0];
        h1 = h1 * prm[64 + e0 + 1] + prm[128 + e0 + 1];
        h0 = 1.0507009873554805f *
             (h0 > 0.f ? h0 : 1.6732632423543772f * (__expf(h0) - 1.f));
        h1 = 1.0507009873554805f *
             (h1 > 0.f ? h1 : 1.6732632423543772f * (__expf(h1) - 1.f));
        *(float2*)(g_h + ((size_t)b * NN + ig) * DD + e0) = make_float2(h0, h1);

        float r = h0 * prm[192 + e0] + h1 * prm[192 + e0 + 1];
        #pragma unroll
        for (int o = 16; o; o >>= 1) r += __shfl_xor_sync(0xffffffffu, r, o);
        if (lane == 0)
            g_scores[b * NN + ig] = 1.f / (1.f + __expf(-(r + prm[320])));
    }

    // ---- last-CTA-of-batch: top-k + gather (fused k3) ----
    __shared__ int is_last;
    __syncthreads();
    if (tid == 0) {
        __threadfence();
        int old = atomicAdd(&g_cnt[b], 1);
        if (old == 7) {
            g_cnt[b] = 0;          // reset for next launch (no races: all 8 done)
            is_last = 1;
        } else {
            is_last = 0;
        }
    }
    __syncthreads();
    if (!is_last) return;
    __threadfence();               // acquire: see all 8 CTAs' g_h / g_scores

    float* sc  = aggs;             // reuse smem
    int*   src = (int*)(aggs + NN);

    float sv = g_scores[b * NN + tid];
    sc[tid] = sv;
    __syncthreads();

    int rank = 0;
    #pragma unroll 8
    for (int j = 0; j < NN; ++j) {
        float sj = sc[j];
        rank += (sj > sv) || (sj == sv && j < tid);
    }
    if (rank < KTOP) src[rank] = tid;
    __syncthreads();

    #pragma unroll
    for (int t = 0; t < 8; ++t) {
        int idx = t * 256 + tid;           // 0 .. 2047 float4s
        int r = idx >> 4, q = idx & 15;
        int j = src[r];
        float wgt = sc[j];
        float4 v = ((const float4*)(g_h + ((size_t)b * NN + j) * DD))[q];
        v.x *= wgt; v.y *= wgt; v.z *= wgt; v.w *= wgt;
        ((float4*)(out + ((size_t)b * KTOP + r) * DD))[q] = v;
    }
}

// =====================================================================
extern "C" void kernel_launch(void* const* d_in, const int* in_sizes, int n_in,
                              void* d_out, int out_size)
{
    const float* x     = (const float*)d_in[0];
    const float* Watt  = (const float*)d_in[1];
    const float* batt  = (const float*)d_in[2];
    const float* attw  = (const float*)d_in[3];
    const float* Wpwa  = (const float*)d_in[4];
    const float* bpwa  = (const float*)d_in[5];
    const float* Wpna  = (const float*)d_in[6];
    const float* bpna  = (const float*)d_in[7];
    const float* bnsc  = (const float*)d_in[8];
    const float* bnbi  = (const float*)d_in[9];
    const float* poolw = (const float*)d_in[10];
    const float* poolb = (const float*)d_in[11];

    cudaFuncSetAttribute(k1a_logits,
                         cudaFuncAttributeMaxDynamicSharedMemorySize, SM_TOT1);
    cudaFuncSetAttribute(k1b2_fused,
                         cudaFuncAttributeMaxDynamicSharedMemorySize, SMB_TOT);

    dim3 ga(NPAIR, BB);
    k1a_logits<<<ga, 256, SM_TOT1>>>(x, Watt, batt, attw);
    dim3 gb(8, BB);
    k1b2_fused<<<gb, 256, SMB_TOT>>>(x, Wpwa, bpwa, Wpna, bpna,
                                     bnsc, bnbi, poolw, poolb,
                                     (float*)d_out);
}

// round 12
// speedup vs baseline: 1.1304x; 1.1304x over previous
#include <cuda_runtime.h>
#include <math.h>
#include <stdint.h>

#define BB   16
#define NN   256
#define DD   64
#define KTOP 128
#define NT   8          // 256/32 tiles per dim
#define NPAIR 36        // NT*(NT+1)/2

// Scratch (no device allocations allowed)
__device__ float g_logits[BB * NN * NN];   // 4 MB
__device__ float g_h[BB * NN * DD];
__device__ float g_scores[BB * NN];

// ---------------- packed f32x2 helpers ----------------
__device__ __forceinline__ unsigned long long pack2f(float a, float b) {
    unsigned long long r;
    asm("mov.b64 %0, {%1, %2};" : "=l"(r) : "f"(a), "f"(b));
    return r;
}
__device__ __forceinline__ void fma2(unsigned long long& d,
                                     unsigned long long a,
                                     unsigned long long b) {
    asm("fma.rn.f32x2 %0, %1, %2, %0;" : "+l"(d) : "l"(a), "l"(b));
}
__device__ __forceinline__ float2 unpack2f(unsigned long long v) {
    float lo, hi;
    asm("mov.b64 {%0, %1}, %2;" : "=f"(lo), "=f"(hi) : "l"(v));
    float2 r; r.x = lo; r.y = hi;
    return r;
}
__device__ __forceinline__ float ex2f(float x) {
    float y; asm("ex2.approx.f32 %0, %1;" : "=f"(y) : "f"(x)); return y;
}
__device__ __forceinline__ float rcpf(float x) {
    float y; asm("rcp.approx.f32 %0, %1;" : "=f"(y) : "f"(x)); return y;
}

#define C2LOG2E 2.8853900817779268f   // 2*log2(e)
#define LOG2E   1.4426950408889634f

// ---------------- k1a smem layout (bytes) ----------------
// xip : [64][16] u64  i-pair scalars             8192
// xj  : [64][36] f32  plain j values (pad 36)    9216
// w2  : [64][36] u64  W natural pairs            18432
// bw2 : 64 float2                                 512
// base: 2 f32 (+pad)                               16
// tile: [32][33] f32                             4224
#define SM_XIP  0
#define SM_XJ   8192
#define SM_W2   17408
#define SM_BW   35840
#define SM_BASE 36352
#define SM_TILE 36368
#define SM_TOT1 (SM_TILE + 4224)

// =====================================================================
// Kernel 1a: symmetric logits. grid (36 tile-pairs, 16 b), block 256.
// Thread: ip = tid>>6, jl = (tid>>1)&31, eh = tid&1.
// Barrier-free pass loop: eh-halves combined via shfl_xor(1) (same warp),
// stores go straight to gmem + mirror tile. One barrier before mirror.
// =====================================================================
__global__ __launch_bounds__(256, 2)
void k1a_logits(const float* __restrict__ x,
                const float* __restrict__ Watt,
                const float* __restrict__ batt_g,
                const float* __restrict__ attw_g)
{
    extern __shared__ char sm[];
    unsigned long long* xip = (unsigned long long*)(sm + SM_XIP);
    float* xjs  = (float*)(sm + SM_XJ);
    unsigned long long* w2 = (unsigned long long*)(sm + SM_W2);
    float2* bw2  = (float2*)(sm + SM_BW);
    float*  base = (float*)(sm + SM_BASE);
    float*  tile = (float*)(sm + SM_TILE);

    const int tid = threadIdx.x;
    const int b   = blockIdx.y;

    // decode triangle tile pair
    int p = blockIdx.x, ti = 0;
    while (p >= NT - ti) { p -= NT - ti; ++ti; }
    const int tj = ti + p;
    const int i0 = ti * 32, j0 = tj * 32;

    const float* xb = x + (size_t)b * NN * DD;

    for (int t = tid; t < 1024; t += 256) {          // xip[d][ipg]
        int ipg = t >> 6, d = t & 63;
        float a = xb[(size_t)(i0 + 2 * ipg) * DD + d];
        float c = xb[(size_t)(i0 + 2 * ipg + 1) * DD + d];
        xip[d * 16 + ipg] = pack2f(a, c);
    }
    for (int t = tid; t < 2048; t += 256) {          // xj[d][j] plain
        int j = t >> 6, d = t & 63;
        xjs[d * 36 + j] = xb[(size_t)(j0 + j) * DD + d];
    }
    for (int t = tid; t < 2048; t += 256) {          // w2[d][slot] natural pairs
        int d = t >> 5, k = t & 31;                  // k = e-pair index
        float2 w = ((const float2*)Watt)[t];         // W[d][2k], W[d][2k+1]
        int slot = (k < 16) ? k : (k + 2);           // eh=1 half at +18
        w2[d * 36 + slot] = pack2f(w.x, w.y);
    }
    if (tid < 64) {
        float aww = attw_g[tid];
        bw2[tid] = make_float2(batt_g[tid] * C2LOG2E, -aww);
    }
    __syncthreads();
    if (tid < 2) {
        float s = 0.f;
        #pragma unroll
        for (int e = 0; e < 32; ++e) s -= bw2[tid * 32 + e].y;   // +aw
        base[tid] = 0.5f * s;
    }
    __syncthreads();

    const int ip = tid >> 6;            // 0..3
    const int jl = (tid >> 1) & 31;     // j lane
    const int eh = tid & 1;             // e half

    const float* xj_p = xjs + jl;
    const char* w_p = (const char*)(w2 + eh * 18);
    const float bs = base[eh];
    const float2* bwh = bw2 + eh * 32;

    #pragma unroll 1
    for (int pass = 0; pass < 4; ++pass) {
        unsigned long long acc0[16], acc1[16];
        #pragma unroll
        for (int k = 0; k < 16; ++k) { acc0[k] = 0ull; acc1[k] = 0ull; }

        const unsigned long long* xv = xip + (pass * 4 + ip);

        #pragma unroll 4
        for (int d = 0; d < 64; ++d) {
            float2 xi2 = unpack2f(xv[d * 16]);
            float xjv = xj_p[d * 36];
            float f0 = xi2.x * xjv, f1 = xi2.y * xjv;
            unsigned long long pp0 = pack2f(f0, f0);
            unsigned long long pp1 = pack2f(f1, f1);
            const ulonglong2* wr = (const ulonglong2*)(w_p + d * 288);
            #pragma unroll
            for (int h = 0; h < 8; ++h) {
                ulonglong2 wv = wr[h];
                fma2(acc0[2 * h + 0], pp0, wv.x);
                fma2(acc0[2 * h + 1], pp0, wv.y);
                fma2(acc1[2 * h + 0], pp1, wv.x);
                fma2(acc1[2 * h + 1], pp1, wv.y);
            }
        }

        // epilogue: tanh + dot(aw); acc lanes = (e, e+1)
        float pl0 = bs, pl1 = bs;
        #pragma unroll
        for (int k = 0; k < 16; ++k) {
            float2 bc0 = bwh[2 * k], bc1 = bwh[2 * k + 1];
            float2 v0 = unpack2f(acc0[k]);
            float2 v1 = unpack2f(acc1[k]);
            float r00 = rcpf(ex2f(fmaf(v0.x, C2LOG2E, bc0.x)) + 1.f);
            float r01 = rcpf(ex2f(fmaf(v0.y, C2LOG2E, bc1.x)) + 1.f);
            float r10 = rcpf(ex2f(fmaf(v1.x, C2LOG2E, bc0.x)) + 1.f);
            float r11 = rcpf(ex2f(fmaf(v1.y, C2LOG2E, bc1.x)) + 1.f);
            pl0 = fmaf(bc0.y, r00, pl0);
            pl0 = fmaf(bc1.y, r01, pl0);
            pl1 = fmaf(bc0.y, r10, pl1);
            pl1 = fmaf(bc1.y, r11, pl1);
        }

        // combine eh halves within the warp (partner = lane^1)
        float full0 = pl0 + __shfl_xor_sync(0xffffffffu, pl0, 1);
        float full1 = pl1 + __shfl_xor_sync(0xffffffffu, pl1, 1);

        // even lane stores row r0, odd lane stores row r0+1 (16B-coalesced
        // per 16-lane parity group); also stage mirror tile
        {
            int r0 = (pass * 4 + ip) * 2;
            int row = r0 + eh;
            float val = eh ? full1 : full0;
            g_logits[((size_t)b * NN + i0 + row) * NN + j0 + jl] = val;
            tile[row * 33 + jl] = val;
        }
        // NO block barrier — pass resources are warp-private
    }
    __syncthreads();

    // coalesced mirror store (off-diagonal tiles only)
    if (ti != tj) {
        #pragma unroll
        for (int k = 0; k < 4; ++k) {
            int jj = (tid >> 5) + k * 8;
            int col = tid & 31;
            g_logits[((size_t)b * NN + j0 + jj) * NN + i0 + col] =
                tile[col * 33 + jj];
        }
    }
}

// ---------------- k1b2 smem layout (bytes) ----------------
#define SMB_XS  0                      // 256*64 f32 = 65536
#define SMB_WA  65536                  // [d][e] 64*64 f32 = 16384
#define SMB_WN  81920                  // 16384
#define SMB_AG  98304                  // [32][64] f32 = 8192
#define SMB_PRM 106496                 // 5*64+8 f32
#define SMB_TOT (106496 + 1312)

// =====================================================================
// Kernel 1b2: softmax + agg + linear + BN + SELU + scores.
// grid (8, 16), block 256 (8 warps). Warp owns 4 i's; barrier-free
// after staging. (round-10 measured best)
// =====================================================================
__global__ __launch_bounds__(256, 2)
void k1b2_fused(const float* __restrict__ x,
                const float* __restrict__ Wpwa, const float* __restrict__ bpwa,
                const float* __restrict__ Wpna, const float* __restrict__ bpna,
                const float* __restrict__ bnsc, const float* __restrict__ bnbi,
                const float* __restrict__ poolw, const float* __restrict__ poolb)
{
    extern __shared__ char sm2[];
    float* xs   = (float*)(sm2 + SMB_XS);
    float* Wa   = (float*)(sm2 + SMB_WA);
    float* Wn   = (float*)(sm2 + SMB_WN);
    float* aggs = (float*)(sm2 + SMB_AG);
    float* prm  = (float*)(sm2 + SMB_PRM);

    const int tid = threadIdx.x;
    const int lane = tid & 31, w = tid >> 5;
    const int b  = blockIdx.y;
    const int i0 = blockIdx.x * 32;
    const float* xb = x + (size_t)b * NN * DD;

    // stage x_b (64KB), W's (natural [d][e] layout), params
    for (int t = tid; t < 4096; t += 256)
        ((float4*)xs)[t] = ((const float4*)xb)[t];
    for (int t = tid; t < 1024; t += 256) {
        ((float4*)Wa)[t] = ((const float4*)Wpwa)[t];
        ((float4*)Wn)[t] = ((const float4*)Wpna)[t];
    }
    if (tid < 64) {
        prm[tid]       = bpwa[tid] + bpna[tid];
        prm[64 + tid]  = bnsc[tid] * rsqrtf(1.0f + 1e-5f);
        prm[128 + tid] = bnbi[tid];
        prm[192 + tid] = poolw[tid];
    }
    if (tid == 0) prm[320] = poolb[0];
    __syncthreads();

    const int d0 = lane * 2;
    const int e0 = lane * 2;

    for (int c = 0; c < 4; ++c) {
        const int iL = w * 4 + c;          // local 0..31
        const int ig = i0 + iL;            // global node

        // ---- softmax over 256 j (warp-only) ----
        const float* lrow = g_logits + ((size_t)b * NN + ig) * NN;
        float4 va = ((const float4*)lrow)[lane];
        float4 vb = ((const float4*)lrow)[32 + lane];
        float av[8] = { va.x, va.y, va.z, va.w, vb.x, vb.y, vb.z, vb.w };

        float m = av[0];
        #pragma unroll
        for (int k = 1; k < 8; ++k) m = fmaxf(m, av[k]);
        #pragma unroll
        for (int o = 16; o; o >>= 1) m = fmaxf(m, __shfl_xor_sync(0xffffffffu, m, o));

        float s = 0.f;
        #pragma unroll
        for (int k = 0; k < 8; ++k) { av[k] = ex2f((av[k] - m) * LOG2E); s += av[k]; }
        #pragma unroll
        for (int o = 16; o; o >>= 1) s += __shfl_xor_sync(0xffffffffu, s, o);
        float inv = 1.f / s;
        #pragma unroll
        for (int k = 0; k < 8; ++k) av[k] *= inv;

        // ---- agg[d0,d0+1] = sum_j A[j] * x[j][d] (smem, shuffle bcast) ----
        float ax0 = 0.f, ay0 = 0.f, ax1 = 0.f, ay1 = 0.f;
        #pragma unroll 4
        for (int src = 0; src < 32; ++src) {
            #pragma unroll
            for (int k = 0; k < 8; ++k) {
                float A = __shfl_sync(0xffffffffu, av[k], src);
                int j = src * 4 + (k & 3) + ((k & 4) << 5);
                float2 xv = *(const float2*)(xs + j * 64 + d0);
                if (k < 4) { ax0 = fmaf(A, xv.x, ax0); ay0 = fmaf(A, xv.y, ay0); }
                else       { ax1 = fmaf(A, xv.x, ax1); ay1 = fmaf(A, xv.y, ay1); }
            }
        }
        *(float2*)(aggs + iL * 64 + d0) = make_float2(ax0 + ax1, ay0 + ay1);
        __syncwarp();

        // ---- linear + BN + SELU + score (warp-only) ----
        float ha0 = 0.f, ha1 = 0.f, hn0 = 0.f, hn1 = 0.f;
        #pragma unroll 8
        for (int d = 0; d < 64; ++d) {
            float ad = aggs[iL * 64 + d];
            float xd = xs[ig * 64 + d];
            float2 wa = *(const float2*)(Wa + d * 64 + e0);
            float2 wn = *(const float2*)(Wn + d * 64 + e0);
            ha0 = fmaf(ad, wa.x, ha0); ha1 = fmaf(ad, wa.y, ha1);
            hn0 = fmaf(xd, wn.x, hn0); hn1 = fmaf(xd, wn.y, hn1);
        }
        float h0 = ha0 + hn0 + prm[e0];
        float h1 = ha1 + hn1 + prm[e0 + 1];
        h0 = h0 * prm[64 + e0] + prm[128 + e0];
        h1 = h1 * prm[64 + e0 + 1] + prm[128 + e0 + 1];
        h0 = 1.0507009873554805f *
             (h0 > 0.f ? h0 : 1.6732632423543772f * (__expf(h0) - 1.f));
        h1 = 1.0507009873554805f *
             (h1 > 0.f ? h1 : 1.6732632423543772f * (__expf(h1) - 1.f));
        *(float2*)(g_h + ((size_t)b * NN + ig) * DD + e0) = make_float2(h0, h1);

        float r = h0 * prm[192 + e0] + h1 * prm[192 + e0 + 1];
        #pragma unroll
        for (int o = 16; o; o >>= 1) r += __shfl_xor_sync(0xffffffffu, r, o);
        if (lane == 0)
            g_scores[b * NN + ig] = 1.f / (1.f + __expf(-(r + prm[320])));
    }
}

// =====================================================================
// Kernel 3: stable top-k + gather. grid (8 slices, 16 b), block 256.
// =====================================================================
__global__ __launch_bounds__(256)
void k3_topk(float* __restrict__ out)
{
    __shared__ float sc[NN];
    __shared__ int src[KTOP];
    const int tid = threadIdx.x;
    const int b = blockIdx.y;
    const int s0 = blockIdx.x * 16;

    float s = g_scores[b * NN + tid];
    sc[tid] = s;
    __syncthreads();

    int rank = 0;
    #pragma unroll 8
    for (int j = 0; j < NN; ++j) {
        float sj = sc[j];
        rank += (sj > s) || (sj == s && j < tid);
    }
    if (rank < KTOP) src[rank] = tid;
    __syncthreads();

    {
        int r = s0 + (tid >> 4), q = tid & 15;
        int j = src[r];
        float w = sc[j];
        float4 v = ((const float4*)(g_h + ((size_t)b * NN + j) * DD))[q];
        v.x *= w; v.y *= w; v.z *= w; v.w *= w;
        ((float4*)(out + ((size_t)b * KTOP + r) * DD))[q] = v;
    }
}

// =====================================================================
extern "C" void kernel_launch(void* const* d_in, const int* in_sizes, int n_in,
                              void* d_out, int out_size)
{
    const float* x     = (const float*)d_in[0];
    const float* Watt  = (const float*)d_in[1];
    const float* batt  = (const float*)d_in[2];
    const float* attw  = (const float*)d_in[3];
    const float* Wpwa  = (const float*)d_in[4];
    const float* bpwa  = (const float*)d_in[5];
    const float* Wpna  = (const float*)d_in[6];
    const float* bpna  = (const float*)d_in[7];
    const float* bnsc  = (const float*)d_in[8];
    const float* bnbi  = (const float*)d_in[9];
    const float* poolw = (const float*)d_in[10];
    const float* poolb = (const float*)d_in[11];

    cudaFuncSetAttribute(k1a_logits,
                         cudaFuncAttributeMaxDynamicSharedMemorySize, SM_TOT1);
    cudaFuncSetAttribute(k1b2_fused,
                         cudaFuncAttributeMaxDynamicSharedMemorySize, SMB_TOT);

    dim3 ga(NPAIR, BB);
    k1a_logits<<<ga, 256, SM_TOT1>>>(x, Watt, batt, attw);
    dim3 gb(8, BB);
    k1b2_fused<<<gb, 256, SMB_TOT>>>(x, Wpwa, bpwa, Wpna, bpna,
                                     bnsc, bnbi, poolw, poolb);
    dim3 gc(8, BB);
    k3_topk<<<gc, 256>>>((float*)d_out);
}

// round 13
// speedup vs baseline: 1.1421x; 1.0104x over previous
#include <cuda_runtime.h>
#include <math.h>
#include <stdint.h>

#define BB   16
#define NN   256
#define DD   64
#define KTOP 128
#define NT   8          // 256/32 tiles per dim
#define NPAIR 36        // NT*(NT+1)/2

// Scratch (no device allocations allowed)
__device__ float g_logits[BB * NN * NN];   // 4 MB
__device__ float g_h[BB * NN * DD];
__device__ float g_scores[BB * NN];

// ---------------- packed f32x2 helpers ----------------
__device__ __forceinline__ unsigned long long pack2f(float a, float b) {
    unsigned long long r;
    asm("mov.b64 %0, {%1, %2};" : "=l"(r) : "f"(a), "f"(b));
    return r;
}
__device__ __forceinline__ void fma2(unsigned long long& d,
                                     unsigned long long a,
                                     unsigned long long b) {
    asm("fma.rn.f32x2 %0, %1, %2, %0;" : "+l"(d) : "l"(a), "l"(b));
}
__device__ __forceinline__ float2 unpack2f(unsigned long long v) {
    float lo, hi;
    asm("mov.b64 {%0, %1}, %2;" : "=f"(lo), "=f"(hi) : "l"(v));
    float2 r; r.x = lo; r.y = hi;
    return r;
}
__device__ __forceinline__ float ex2f(float x) {
    float y; asm("ex2.approx.f32 %0, %1;" : "=f"(y) : "f"(x)); return y;
}
__device__ __forceinline__ float rcpf(float x) {
    float y; asm("rcp.approx.f32 %0, %1;" : "=f"(y) : "f"(x)); return y;
}

#define C2LOG2E 2.8853900817779268f   // 2*log2(e)
#define LOG2E   1.4426950408889634f

// ---------------- k1a smem layout (bytes) ----------------
#define SM_XIP  0
#define SM_XJ   8192
#define SM_W2   17408
#define SM_BW   35840
#define SM_BASE 36352
#define SM_TILE 36368
#define SM_TOT1 (SM_TILE + 4224)

// =====================================================================
// Kernel 1a: symmetric logits. grid (36 tile-pairs, 16 b), block 256.
// (round-12 measured best — byte-identical compute)
// =====================================================================
__global__ __launch_bounds__(256, 2)
void k1a_logits(const float* __restrict__ x,
                const float* __restrict__ Watt,
                const float* __restrict__ batt_g,
                const float* __restrict__ attw_g)
{
    extern __shared__ char sm[];
    unsigned long long* xip = (unsigned long long*)(sm + SM_XIP);
    float* xjs  = (float*)(sm + SM_XJ);
    unsigned long long* w2 = (unsigned long long*)(sm + SM_W2);
    float2* bw2  = (float2*)(sm + SM_BW);
    float*  base = (float*)(sm + SM_BASE);
    float*  tile = (float*)(sm + SM_TILE);

    const int tid = threadIdx.x;
    const int b   = blockIdx.y;

    int p = blockIdx.x, ti = 0;
    while (p >= NT - ti) { p -= NT - ti; ++ti; }
    const int tj = ti + p;
    const int i0 = ti * 32, j0 = tj * 32;

    const float* xb = x + (size_t)b * NN * DD;

    for (int t = tid; t < 1024; t += 256) {          // xip[d][ipg]
        int ipg = t >> 6, d = t & 63;
        float a = xb[(size_t)(i0 + 2 * ipg) * DD + d];
        float c = xb[(size_t)(i0 + 2 * ipg + 1) * DD + d];
        xip[d * 16 + ipg] = pack2f(a, c);
    }
    for (int t = tid; t < 2048; t += 256) {          // xj[d][j] plain
        int j = t >> 6, d = t & 63;
        xjs[d * 36 + j] = xb[(size_t)(j0 + j) * DD + d];
    }
    for (int t = tid; t < 2048; t += 256) {          // w2[d][slot] natural pairs
        int d = t >> 5, k = t & 31;
        float2 w = ((const float2*)Watt)[t];
        int slot = (k < 16) ? k : (k + 2);           // eh=1 half at +18
        w2[d * 36 + slot] = pack2f(w.x, w.y);
    }
    if (tid < 64) {
        float aww = attw_g[tid];
        bw2[tid] = make_float2(batt_g[tid] * C2LOG2E, -aww);
    }
    __syncthreads();
    if (tid < 2) {
        float s = 0.f;
        #pragma unroll
        for (int e = 0; e < 32; ++e) s -= bw2[tid * 32 + e].y;   // +aw
        base[tid] = 0.5f * s;
    }
    __syncthreads();

    const int ip = tid >> 6;            // 0..3
    const int jl = (tid >> 1) & 31;     // j lane
    const int eh = tid & 1;             // e half

    const float* xj_p = xjs + jl;
    const char* w_p = (const char*)(w2 + eh * 18);
    const float bs = base[eh];
    const float2* bwh = bw2 + eh * 32;

    #pragma unroll 1
    for (int pass = 0; pass < 4; ++pass) {
        unsigned long long acc0[16], acc1[16];
        #pragma unroll
        for (int k = 0; k < 16; ++k) { acc0[k] = 0ull; acc1[k] = 0ull; }

        const unsigned long long* xv = xip + (pass * 4 + ip);

        #pragma unroll 4
        for (int d = 0; d < 64; ++d) {
            float2 xi2 = unpack2f(xv[d * 16]);
            float xjv = xj_p[d * 36];
            float f0 = xi2.x * xjv, f1 = xi2.y * xjv;
            unsigned long long pp0 = pack2f(f0, f0);
            unsigned long long pp1 = pack2f(f1, f1);
            const ulonglong2* wr = (const ulonglong2*)(w_p + d * 288);
            #pragma unroll
            for (int h = 0; h < 8; ++h) {
                ulonglong2 wv = wr[h];
                fma2(acc0[2 * h + 0], pp0, wv.x);
                fma2(acc0[2 * h + 1], pp0, wv.y);
                fma2(acc1[2 * h + 0], pp1, wv.x);
                fma2(acc1[2 * h + 1], pp1, wv.y);
            }
        }

        float pl0 = bs, pl1 = bs;
        #pragma unroll
        for (int k = 0; k < 16; ++k) {
            float2 bc0 = bwh[2 * k], bc1 = bwh[2 * k + 1];
            float2 v0 = unpack2f(acc0[k]);
            float2 v1 = unpack2f(acc1[k]);
            float r00 = rcpf(ex2f(fmaf(v0.x, C2LOG2E, bc0.x)) + 1.f);
            float r01 = rcpf(ex2f(fmaf(v0.y, C2LOG2E, bc1.x)) + 1.f);
            float r10 = rcpf(ex2f(fmaf(v1.x, C2LOG2E, bc0.x)) + 1.f);
            float r11 = rcpf(ex2f(fmaf(v1.y, C2LOG2E, bc1.x)) + 1.f);
            pl0 = fmaf(bc0.y, r00, pl0);
            pl0 = fmaf(bc1.y, r01, pl0);
            pl1 = fmaf(bc0.y, r10, pl1);
            pl1 = fmaf(bc1.y, r11, pl1);
        }

        float full0 = pl0 + __shfl_xor_sync(0xffffffffu, pl0, 1);
        float full1 = pl1 + __shfl_xor_sync(0xffffffffu, pl1, 1);

        {
            int r0 = (pass * 4 + ip) * 2;
            int row = r0 + eh;
            float val = eh ? full1 : full0;
            g_logits[((size_t)b * NN + i0 + row) * NN + j0 + jl] = val;
            tile[row * 33 + jl] = val;
        }
    }
    __syncthreads();

    if (ti != tj) {
        #pragma unroll
        for (int k = 0; k < 4; ++k) {
            int jj = (tid >> 5) + k * 8;
            int col = tid & 31;
            g_logits[((size_t)b * NN + j0 + jj) * NN + i0 + col] =
                tile[col * 33 + jj];
        }
    }
}

// ---------------- k1b2 smem layout (bytes) ----------------
#define SMB_XS  0                      // 256*64 f32 = 65536
#define SMB_WA  65536
#define SMB_WN  81920
#define SMB_AG  98304
#define SMB_PRM 106496
#define SMB_TOT (106496 + 1312)

// =====================================================================
// Kernel 1b2: softmax + agg + linear + BN + SELU + scores.
// PDL: staging overlaps k1a; gridDepSync gates g_logits reads.
// =====================================================================
__global__ __launch_bounds__(256, 2)
void k1b2_fused(const float* __restrict__ x,
                const float* __restrict__ Wpwa, const float* __restrict__ bpwa,
                const float* __restrict__ Wpna, const float* __restrict__ bpna,
                const float* __restrict__ bnsc, const float* __restrict__ bnbi,
                const float* __restrict__ poolw, const float* __restrict__ poolb)
{
    extern __shared__ char sm2[];
    float* xs   = (float*)(sm2 + SMB_XS);
    float* Wa   = (float*)(sm2 + SMB_WA);
    float* Wn   = (float*)(sm2 + SMB_WN);
    float* aggs = (float*)(sm2 + SMB_AG);
    float* prm  = (float*)(sm2 + SMB_PRM);

    const int tid = threadIdx.x;
    const int lane = tid & 31, w = tid >> 5;
    const int b  = blockIdx.y;
    const int i0 = blockIdx.x * 32;
    const float* xb = x + (size_t)b * NN * DD;

    // stage x_b (64KB), W's, params — independent of k1a's output
    for (int t = tid; t < 4096; t += 256)
        ((float4*)xs)[t] = ((const float4*)xb)[t];
    for (int t = tid; t < 1024; t += 256) {
        ((float4*)Wa)[t] = ((const float4*)Wpwa)[t];
        ((float4*)Wn)[t] = ((const float4*)Wpna)[t];
    }
    if (tid < 64) {
        prm[tid]       = bpwa[tid] + bpna[tid];
        prm[64 + tid]  = bnsc[tid] * rsqrtf(1.0f + 1e-5f);
        prm[128 + tid] = bnbi[tid];
        prm[192 + tid] = poolw[tid];
    }
    if (tid == 0) prm[320] = poolb[0];

    // wait for k1a (PDL edge) before touching g_logits
    cudaGridDependencySynchronize();
    __syncthreads();

    const int d0 = lane * 2;
    const int e0 = lane * 2;

    for (int c = 0; c < 4; ++c) {
        const int iL = w * 4 + c;
        const int ig = i0 + iL;

        const float* lrow = g_logits + ((size_t)b * NN + ig) * NN;
        float4 va = ((const float4*)lrow)[lane];
        float4 vb = ((const float4*)lrow)[32 + lane];
        float av[8] = { va.x, va.y, va.z, va.w, vb.x, vb.y, vb.z, vb.w };

        float m = av[0];
        #pragma unroll
        for (int k = 1; k < 8; ++k) m = fmaxf(m, av[k]);
        #pragma unroll
        for (int o = 16; o; o >>= 1) m = fmaxf(m, __shfl_xor_sync(0xffffffffu, m, o));

        float s = 0.f;
        #pragma unroll
        for (int k = 0; k < 8; ++k) { av[k] = ex2f((av[k] - m) * LOG2E); s += av[k]; }
        #pragma unroll
        for (int o = 16; o; o >>= 1) s += __shfl_xor_sync(0xffffffffu, s, o);
        float inv = 1.f / s;
        #pragma unroll
        for (int k = 0; k < 8; ++k) av[k] *= inv;

        float ax0 = 0.f, ay0 = 0.f, ax1 = 0.f, ay1 = 0.f;
        #pragma unroll 4
        for (int src = 0; src < 32; ++src) {
            #pragma unroll
            for (int k = 0; k < 8; ++k) {
                float A = __shfl_sync(0xffffffffu, av[k], src);
                int j = src * 4 + (k & 3) + ((k & 4) << 5);
                float2 xv = *(const float2*)(xs + j * 64 + d0);
                if (k < 4) { ax0 = fmaf(A, xv.x, ax0); ay0 = fmaf(A, xv.y, ay0); }
                else       { ax1 = fmaf(A, xv.x, ax1); ay1 = fmaf(A, xv.y, ay1); }
            }
        }
        *(float2*)(aggs + iL * 64 + d0) = make_float2(ax0 + ax1, ay0 + ay1);
        __syncwarp();

        float ha0 = 0.f, ha1 = 0.f, hn0 = 0.f, hn1 = 0.f;
        #pragma unroll 8
        for (int d = 0; d < 64; ++d) {
            float ad = aggs[iL * 64 + d];
            float xd = xs[ig * 64 + d];
            float2 wa = *(const float2*)(Wa + d * 64 + e0);
            float2 wn = *(const float2*)(Wn + d * 64 + e0);
            ha0 = fmaf(ad, wa.x, ha0); ha1 = fmaf(ad, wa.y, ha1);
            hn0 = fmaf(xd, wn.x, hn0); hn1 = fmaf(xd, wn.y, hn1);
        }
        float h0 = ha0 + hn0 + prm[e0];
        float h1 = ha1 + hn1 + prm[e0 + 1];
        h0 = h0 * prm[64 + e0] + prm[128 + e0];
        h1 = h1 * prm[64 + e0 + 1] + prm[128 + e0 + 1];
        h0 = 1.0507009873554805f *
             (h0 > 0.f ? h0 : 1.6732632423543772f * (__expf(h0) - 1.f));
        h1 = 1.0507009873554805f *
             (h1 > 0.f ? h1 : 1.6732632423543772f * (__expf(h1) - 1.f));
        *(float2*)(g_h + ((size_t)b * NN + ig) * DD + e0) = make_float2(h0, h1);

        float r = h0 * prm[192 + e0] + h1 * prm[192 + e0 + 1];
        #pragma unroll
        for (int o = 16; o; o >>= 1) r += __shfl_xor_sync(0xffffffffu, r, o);
        if (lane == 0)
            g_scores[b * NN + ig] = 1.f / (1.f + __expf(-(r + prm[320])));
    }
}

// =====================================================================
// Kernel 3: stable top-k + gather. grid (8 slices, 16 b), block 256.
// PDL: launch overlaps k1b2; gridDepSync before reading scores.
// =====================================================================
__global__ __launch_bounds__(256)
void k3_topk(float* __restrict__ out)
{
    __shared__ float sc[NN];
    __shared__ int src[KTOP];
    const int tid = threadIdx.x;
    const int b = blockIdx.y;
    const int s0 = blockIdx.x * 16;

    cudaGridDependencySynchronize();

    float s = g_scores[b * NN + tid];
    sc[tid] = s;
    __syncthreads();

    int rank = 0;
    #pragma unroll 8
    for (int j = 0; j < NN; ++j) {
        float sj = sc[j];
        rank += (sj > s) || (sj == s && j < tid);
    }
    if (rank < KTOP) src[rank] = tid;
    __syncthreads();

    {
        int r = s0 + (tid >> 4), q = tid & 15;
        int j = src[r];
        float w = sc[j];
        float4 v = ((const float4*)(g_h + ((size_t)b * NN + j) * DD))[q];
        v.x *= w; v.y *= w; v.z *= w; v.w *= w;
        ((float4*)(out + ((size_t)b * KTOP + r) * DD))[q] = v;
    }
}

// =====================================================================
extern "C" void kernel_launch(void* const* d_in, const int* in_sizes, int n_in,
                              void* d_out, int out_size)
{
    const float* x     = (const float*)d_in[0];
    const float* Watt  = (const float*)d_in[1];
    const float* batt  = (const float*)d_in[2];
    const float* attw  = (const float*)d_in[3];
    const float* Wpwa  = (const float*)d_in[4];
    const float* bpwa  = (const float*)d_in[5];
    const float* Wpna  = (const float*)d_in[6];
    const float* bpna  = (const float*)d_in[7];
    const float* bnsc  = (const float*)d_in[8];
    const float* bnbi  = (const float*)d_in[9];
    const float* poolw = (const float*)d_in[10];
    const float* poolb = (const float*)d_in[11];
    float* out = (float*)d_out;

    cudaFuncSetAttribute(k1a_logits,
                         cudaFuncAttributeMaxDynamicSharedMemorySize, SM_TOT1);
    cudaFuncSetAttribute(k1b2_fused,
                         cudaFuncAttributeMaxDynamicSharedMemorySize, SMB_TOT);

    dim3 ga(NPAIR, BB);
    k1a_logits<<<ga, 256, SM_TOT1>>>(x, Watt, batt, attw);

    // k1b2 with PDL: staging overlaps k1a's tail
    {
        cudaLaunchConfig_t cfg = {};
        cfg.gridDim = dim3(8, BB, 1);
        cfg.blockDim = dim3(256, 1, 1);
        cfg.dynamicSmemBytes = SMB_TOT;
        cfg.stream = 0;
        cudaLaunchAttribute attr[1];
        attr[0].id = cudaLaunchAttributeProgrammaticStreamSerialization;
        attr[0].val.programmaticStreamSerializationAllowed = 1;
        cfg.attrs = attr;
        cfg.numAttrs = 1;
        cudaLaunchKernelEx(&cfg, k1b2_fused, x, Wpwa, bpwa, Wpna, bpna,
                           bnsc, bnbi, poolw, poolb);
    }

    // k3 with PDL: launch overlaps k1b2
    {
        cudaLaunchConfig_t cfg = {};
        cfg.gridDim = dim3(8, BB, 1);
        cfg.blockDim = dim3(256, 1, 1);
        cfg.dynamicSmemBytes = 0;
        cfg.stream = 0;
        cudaLaunchAttribute attr[1];
        attr[0].id = cudaLaunchAttributeProgrammaticStreamSerialization;
        attr[0].val.programmaticStreamSerializationAllowed = 1;
        cfg.attrs = attr;
        cfg.numAttrs = 1;
        cudaLaunchKernelEx(&cfg, k3_topk, out);
    }
}

// round 14
// speedup vs baseline: 1.1447x; 1.0023x over previous
#include <cuda_runtime.h>
#include <math.h>
#include <stdint.h>

#define BB   16
#define NN   256
#define DD   64
#define KTOP 128
#define NT   8          // 256/32 tiles per dim
#define NPAIR 36        // NT*(NT+1)/2

// Scratch (no device allocations allowed)
__device__ float g_logits[BB * NN * NN];   // 4 MB
__device__ float g_h[BB * NN * DD];
__device__ float g_scores[BB * NN];

// ---------------- packed f32x2 helpers ----------------
__device__ __forceinline__ unsigned long long pack2f(float a, float b) {
    unsigned long long r;
    asm("mov.b64 %0, {%1, %2};" : "=l"(r) : "f"(a), "f"(b));
    return r;
}
__device__ __forceinline__ void fma2(unsigned long long& d,
                                     unsigned long long a,
                                     unsigned long long b) {
    asm("fma.rn.f32x2 %0, %1, %2, %0;" : "+l"(d) : "l"(a), "l"(b));
}
__device__ __forceinline__ float2 unpack2f(unsigned long long v) {
    float lo, hi;
    asm("mov.b64 {%0, %1}, %2;" : "=f"(lo), "=f"(hi) : "l"(v));
    float2 r; r.x = lo; r.y = hi;
    return r;
}
__device__ __forceinline__ float ex2f(float x) {
    float y; asm("ex2.approx.f32 %0, %1;" : "=f"(y) : "f"(x)); return y;
}
__device__ __forceinline__ float rcpf(float x) {
    float y; asm("rcp.approx.f32 %0, %1;" : "=f"(y) : "f"(x)); return y;
}

#define C2LOG2E 2.8853900817779268f   // 2*log2(e)
#define LOG2E   1.4426950408889634f

// ---------------- k1a smem layout (bytes) ----------------
#define SM_XIP  0
#define SM_XJ   8192
#define SM_W2   17408
#define SM_BW   35840
#define SM_BASE 36352
#define SM_TILE 36368
#define SM_TOT1 (SM_TILE + 4224)

// =====================================================================
// Kernel 1a: symmetric logits. grid (36 tile-pairs, 16 b), block 256.
// (round-12 measured best — byte-identical compute)
// =====================================================================
__global__ __launch_bounds__(256, 2)
void k1a_logits(const float* __restrict__ x,
                const float* __restrict__ Watt,
                const float* __restrict__ batt_g,
                const float* __restrict__ attw_g)
{
    extern __shared__ char sm[];
    unsigned long long* xip = (unsigned long long*)(sm + SM_XIP);
    float* xjs  = (float*)(sm + SM_XJ);
    unsigned long long* w2 = (unsigned long long*)(sm + SM_W2);
    float2* bw2  = (float2*)(sm + SM_BW);
    float*  base = (float*)(sm + SM_BASE);
    float*  tile = (float*)(sm + SM_TILE);

    const int tid = threadIdx.x;
    const int b   = blockIdx.y;

    int p = blockIdx.x, ti = 0;
    while (p >= NT - ti) { p -= NT - ti; ++ti; }
    const int tj = ti + p;
    const int i0 = ti * 32, j0 = tj * 32;

    const float* xb = x + (size_t)b * NN * DD;

    for (int t = tid; t < 1024; t += 256) {          // xip[d][ipg]
        int ipg = t >> 6, d = t & 63;
        float a = xb[(size_t)(i0 + 2 * ipg) * DD + d];
        float c = xb[(size_t)(i0 + 2 * ipg + 1) * DD + d];
        xip[d * 16 + ipg] = pack2f(a, c);
    }
    for (int t = tid; t < 2048; t += 256) {          // xj[d][j] plain
        int j = t >> 6, d = t & 63;
        xjs[d * 36 + j] = xb[(size_t)(j0 + j) * DD + d];
    }
    for (int t = tid; t < 2048; t += 256) {          // w2[d][slot] natural pairs
        int d = t >> 5, k = t & 31;
        float2 w = ((const float2*)Watt)[t];
        int slot = (k < 16) ? k : (k + 2);           // eh=1 half at +18
        w2[d * 36 + slot] = pack2f(w.x, w.y);
    }
    if (tid < 64) {
        float aww = attw_g[tid];
        bw2[tid] = make_float2(batt_g[tid] * C2LOG2E, -aww);
    }
    __syncthreads();
    if (tid < 2) {
        float s = 0.f;
        #pragma unroll
        for (int e = 0; e < 32; ++e) s -= bw2[tid * 32 + e].y;   // +aw
        base[tid] = 0.5f * s;
    }
    __syncthreads();

    const int ip = tid >> 6;            // 0..3
    const int jl = (tid >> 1) & 31;     // j lane
    const int eh = tid & 1;             // e half

    const float* xj_p = xjs + jl;
    const char* w_p = (const char*)(w2 + eh * 18);
    const float bs = base[eh];
    const float2* bwh = bw2 + eh * 32;

    #pragma unroll 1
    for (int pass = 0; pass < 4; ++pass) {
        unsigned long long acc0[16], acc1[16];
        #pragma unroll
        for (int k = 0; k < 16; ++k) { acc0[k] = 0ull; acc1[k] = 0ull; }

        const unsigned long long* xv = xip + (pass * 4 + ip);

        #pragma unroll 4
        for (int d = 0; d < 64; ++d) {
            float2 xi2 = unpack2f(xv[d * 16]);
            float xjv = xj_p[d * 36];
            float f0 = xi2.x * xjv, f1 = xi2.y * xjv;
            unsigned long long pp0 = pack2f(f0, f0);
            unsigned long long pp1 = pack2f(f1, f1);
            const ulonglong2* wr = (const ulonglong2*)(w_p + d * 288);
            #pragma unroll
            for (int h = 0; h < 8; ++h) {
                ulonglong2 wv = wr[h];
                fma2(acc0[2 * h + 0], pp0, wv.x);
                fma2(acc0[2 * h + 1], pp0, wv.y);
                fma2(acc1[2 * h + 0], pp1, wv.x);
                fma2(acc1[2 * h + 1], pp1, wv.y);
            }
        }

        float pl0 = bs, pl1 = bs;
        #pragma unroll
        for (int k = 0; k < 16; ++k) {
            float2 bc0 = bwh[2 * k], bc1 = bwh[2 * k + 1];
            float2 v0 = unpack2f(acc0[k]);
            float2 v1 = unpack2f(acc1[k]);
            float r00 = rcpf(ex2f(fmaf(v0.x, C2LOG2E, bc0.x)) + 1.f);
            float r01 = rcpf(ex2f(fmaf(v0.y, C2LOG2E, bc1.x)) + 1.f);
            float r10 = rcpf(ex2f(fmaf(v1.x, C2LOG2E, bc0.x)) + 1.f);
            float r11 = rcpf(ex2f(fmaf(v1.y, C2LOG2E, bc1.x)) + 1.f);
            pl0 = fmaf(bc0.y, r00, pl0);
            pl0 = fmaf(bc1.y, r01, pl0);
            pl1 = fmaf(bc0.y, r10, pl1);
            pl1 = fmaf(bc1.y, r11, pl1);
        }

        float full0 = pl0 + __shfl_xor_sync(0xffffffffu, pl0, 1);
        float full1 = pl1 + __shfl_xor_sync(0xffffffffu, pl1, 1);

        {
            int r0 = (pass * 4 + ip) * 2;
            int row = r0 + eh;
            float val = eh ? full1 : full0;
            g_logits[((size_t)b * NN + i0 + row) * NN + j0 + jl] = val;
            tile[row * 33 + jl] = val;
        }
    }
    __syncthreads();

    if (ti != tj) {
        #pragma unroll
        for (int k = 0; k < 4; ++k) {
            int jj = (tid >> 5) + k * 8;
            int col = tid & 31;
            g_logits[((size_t)b * NN + j0 + jj) * NN + i0 + col] =
                tile[col * 33 + jj];
        }
    }
}

// ---------------- k1b2 smem layout (bytes) ----------------
#define SMB_XS  0                      // 256*64 f32 = 65536
#define SMB_WA  65536
#define SMB_WN  81920
#define SMB_AG  98304                  // [16][64] f32 = 4096
#define SMB_PRM 102400
#define SMB_TOT (102400 + 1312)

// =====================================================================
// Kernel 1b2: softmax + agg + linear + BN + SELU + scores.
// grid (16, 16), block 256 (8 warps). Warp owns 2 i's; barrier-free
// after staging. PDL gates g_logits reads.
// =====================================================================
__global__ __launch_bounds__(256, 2)
void k1b2_fused(const float* __restrict__ x,
                const float* __restrict__ Wpwa, const float* __restrict__ bpwa,
                const float* __restrict__ Wpna, const float* __restrict__ bpna,
                const float* __restrict__ bnsc, const float* __restrict__ bnbi,
                const float* __restrict__ poolw, const float* __restrict__ poolb)
{
    extern __shared__ char sm2[];
    float* xs   = (float*)(sm2 + SMB_XS);
    float* Wa   = (float*)(sm2 + SMB_WA);
    float* Wn   = (float*)(sm2 + SMB_WN);
    float* aggs = (float*)(sm2 + SMB_AG);
    float* prm  = (float*)(sm2 + SMB_PRM);

    const int tid = threadIdx.x;
    const int lane = tid & 31, w = tid >> 5;
    const int b  = blockIdx.y;
    const int i0 = blockIdx.x * 16;
    const float* xb = x + (size_t)b * NN * DD;

    // stage x_b (64KB), W's, params — independent of k1a's output
    for (int t = tid; t < 4096; t += 256)
        ((float4*)xs)[t] = ((const float4*)xb)[t];
    for (int t = tid; t < 1024; t += 256) {
        ((float4*)Wa)[t] = ((const float4*)Wpwa)[t];
        ((float4*)Wn)[t] = ((const float4*)Wpna)[t];
    }
    if (tid < 64) {
        prm[tid]       = bpwa[tid] + bpna[tid];
        prm[64 + tid]  = bnsc[tid] * rsqrtf(1.0f + 1e-5f);
        prm[128 + tid] = bnbi[tid];
        prm[192 + tid] = poolw[tid];
    }
    if (tid == 0) prm[320] = poolb[0];

    // wait for k1a (PDL edge) before touching g_logits
    cudaGridDependencySynchronize();
    __syncthreads();

    const int d0 = lane * 2;
    const int e0 = lane * 2;

    for (int c = 0; c < 2; ++c) {
        const int iL = w * 2 + c;          // local 0..15
        const int ig = i0 + iL;            // global node

        const float* lrow = g_logits + ((size_t)b * NN + ig) * NN;
        float4 va = ((const float4*)lrow)[lane];
        float4 vb = ((const float4*)lrow)[32 + lane];
        float av[8] = { va.x, va.y, va.z, va.w, vb.x, vb.y, vb.z, vb.w };

        float m = av[0];
        #pragma unroll
        for (int k = 1; k < 8; ++k) m = fmaxf(m, av[k]);
        #pragma unroll
        for (int o = 16; o; o >>= 1) m = fmaxf(m, __shfl_xor_sync(0xffffffffu, m, o));

        float s = 0.f;
        #pragma unroll
        for (int k = 0; k < 8; ++k) { av[k] = ex2f((av[k] - m) * LOG2E); s += av[k]; }
        #pragma unroll
        for (int o = 16; o; o >>= 1) s += __shfl_xor_sync(0xffffffffu, s, o);
        float inv = 1.f / s;
        #pragma unroll
        for (int k = 0; k < 8; ++k) av[k] *= inv;

        float ax0 = 0.f, ay0 = 0.f, ax1 = 0.f, ay1 = 0.f;
        #pragma unroll 4
        for (int src = 0; src < 32; ++src) {
            #pragma unroll
            for (int k = 0; k < 8; ++k) {
                float A = __shfl_sync(0xffffffffu, av[k], src);
                int j = src * 4 + (k & 3) + ((k & 4) << 5);
                float2 xv = *(const float2*)(xs + j * 64 + d0);
                if (k < 4) { ax0 = fmaf(A, xv.x, ax0); ay0 = fmaf(A, xv.y, ay0); }
                else       { ax1 = fmaf(A, xv.x, ax1); ay1 = fmaf(A, xv.y, ay1); }
            }
        }
        *(float2*)(aggs + iL * 64 + d0) = make_float2(ax0 + ax1, ay0 + ay1);
        __syncwarp();

        float ha0 = 0.f, ha1 = 0.f, hn0 = 0.f, hn1 = 0.f;
        #pragma unroll 8
        for (int d = 0; d < 64; ++d) {
            float ad = aggs[iL * 64 + d];
            float xd = xs[ig * 64 + d];
            float2 wa = *(const float2*)(Wa + d * 64 + e0);
            float2 wn = *(const float2*)(Wn + d * 64 + e0);
            ha0 = fmaf(ad, wa.x, ha0); ha1 = fmaf(ad, wa.y, ha1);
            hn0 = fmaf(xd, wn.x, hn0); hn1 = fmaf(xd, wn.y, hn1);
        }
        float h0 = ha0 + hn0 + prm[e0];
        float h1 = ha1 + hn1 + prm[e0 + 1];
        h0 = h0 * prm[64 + e0] + prm[128 + e0];
        h1 = h1 * prm[64 + e0 + 1] + prm[128 + e0 + 1];
        h0 = 1.0507009873554805f *
             (h0 > 0.f ? h0 : 1.6732632423543772f * (__expf(h0) - 1.f));
        h1 = 1.0507009873554805f *
             (h1 > 0.f ? h1 : 1.6732632423543772f * (__expf(h1) - 1.f));
        *(float2*)(g_h + ((size_t)b * NN + ig) * DD + e0) = make_float2(h0, h1);

        float r = h0 * prm[192 + e0] + h1 * prm[192 + e0 + 1];
        #pragma unroll
        for (int o = 16; o; o >>= 1) r += __shfl_xor_sync(0xffffffffu, r, o);
        if (lane == 0)
            g_scores[b * NN + ig] = 1.f / (1.f + __expf(-(r + prm[320])));
    }
}

// =====================================================================
// Kernel 3: stable top-k + gather. grid (8 slices, 16 b), block 256.
// PDL: launch overlaps k1b2; gridDepSync before reading scores.
// =====================================================================
__global__ __launch_bounds__(256)
void k3_topk(float* __restrict__ out)
{
    __shared__ float sc[NN];
    __shared__ int src[KTOP];
    const int tid = threadIdx.x;
    const int b = blockIdx.y;
    const int s0 = blockIdx.x * 16;

    cudaGridDependencySynchronize();

    float s = g_scores[b * NN + tid];
    sc[tid] = s;
    __syncthreads();

    int rank = 0;
    #pragma unroll 8
    for (int j = 0; j < NN; ++j) {
        float sj = sc[j];
        rank += (sj > s) || (sj == s && j < tid);
    }
    if (rank < KTOP) src[rank] = tid;
    __syncthreads();

    {
        int r = s0 + (tid >> 4), q = tid & 15;
        int j = src[r];
        float w = sc[j];
        float4 v = ((const float4*)(g_h + ((size_t)b * NN + j) * DD))[q];
        v.x *= w; v.y *= w; v.z *= w; v.w *= w;
        ((float4*)(out + ((size_t)b * KTOP + r) * DD))[q] = v;
    }
}

// =====================================================================
extern "C" void kernel_launch(void* const* d_in, const int* in_sizes, int n_in,
                              void* d_out, int out_size)
{
    const float* x     = (const float*)d_in[0];
    const float* Watt  = (const float*)d_in[1];
    const float* batt  = (const float*)d_in[2];
    const float* attw  = (const float*)d_in[3];
    const float* Wpwa  = (const float*)d_in[4];
    const float* bpwa  = (const float*)d_in[5];
    const float* Wpna  = (const float*)d_in[6];
    const float* bpna  = (const float*)d_in[7];
    const float* bnsc  = (const float*)d_in[8];
    const float* bnbi  = (const float*)d_in[9];
    const float* poolw = (const float*)d_in[10];
    const float* poolb = (const float*)d_in[11];
    float* out = (float*)d_out;

    cudaFuncSetAttribute(k1a_logits,
                         cudaFuncAttributeMaxDynamicSharedMemorySize, SM_TOT1);
    cudaFuncSetAttribute(k1b2_fused,
                         cudaFuncAttributeMaxDynamicSharedMemorySize, SMB_TOT);

    dim3 ga(NPAIR, BB);
    k1a_logits<<<ga, 256, SM_TOT1>>>(x, Watt, batt, attw);

    // k1b2 with PDL: staging overlaps k1a's tail
    {
        cudaLaunchConfig_t cfg = {};
        cfg.gridDim = dim3(16, BB, 1);
        cfg.blockDim = dim3(256, 1, 1);
        cfg.dynamicSmemBytes = SMB_TOT;
        cfg.stream = 0;
        cudaLaunchAttribute attr[1];
        attr[0].id = cudaLaunchAttributeProgrammaticStreamSerialization;
        attr[0].val.programmaticStreamSerializationAllowed = 1;
        cfg.attrs = attr;
        cfg.numAttrs = 1;
        cudaLaunchKernelEx(&cfg, k1b2_fused, x, Wpwa, bpwa, Wpna, bpna,
                           bnsc, bnbi, poolw, poolb);
    }

    // k3 with PDL: launch overlaps k1b2
    {
        cudaLaunchConfig_t cfg = {};
        cfg.gridDim = dim3(8, BB, 1);
        cfg.blockDim = dim3(256, 1, 1);
        cfg.dynamicSmemBytes = 0;
        cfg.stream = 0;
        cudaLaunchAttribute attr[1];
        attr[0].id = cudaLaunchAttributeProgrammaticStreamSerialization;
        attr[0].val.programmaticStreamSerializationAllowed = 1;
        cfg.attrs = attr;
        cfg.numAttrs = 1;
        cudaLaunchKernelEx(&cfg, k3_topk, out);
    }
}